// round 1
// baseline (speedup 1.0000x reference)
#include <cuda_runtime.h>
#include <math.h>

#define BB 2
#define CC 256
#define NHEADS 8
#define HD 32
#define NN 1600
#define C3 768
#define BH 16
#define SCALE 0.17677669529663687f  // 1/sqrt(32)

// ---------------- scratch (static device memory; no allocations) ----------------
__device__ float g_qkv0[BB * C3 * NN];             // after 1x1 conv
__device__ float g_qkv1[BB * C3 * NN];             // after depthwise 3x3
__device__ float g_attn[(size_t)BH * NN * NN];     // 163.84 MB: attn, then p in-place
__device__ float g_rowmax[BH * NN];
__device__ float g_ent[BH * NN];
__device__ int   g_keep[BH];
__device__ float g_attout[BB * NN * CC];           // [b][pixel][c] pre-projection

// ---------------- helpers ----------------
__device__ __forceinline__ unsigned int f2key(float f) {
    unsigned int u = __float_as_uint(f);
    return (u & 0x80000000u) ? ~u : (u | 0x80000000u);
}

__device__ __forceinline__ float bsum(float v, volatile float* sh) {
    #pragma unroll
    for (int o = 16; o; o >>= 1) v += __shfl_xor_sync(0xffffffffu, v, o);
    if ((threadIdx.x & 31) == 0) sh[threadIdx.x >> 5] = v;
    __syncthreads();
    if (threadIdx.x == 0) {
        float r = 0.f;
        #pragma unroll
        for (int i = 0; i < 8; i++) r += sh[i];
        sh[0] = r;
    }
    __syncthreads();
    float r = sh[0];
    __syncthreads();
    return r;
}

__device__ __forceinline__ float bmax(float v, volatile float* sh) {
    #pragma unroll
    for (int o = 16; o; o >>= 1) v = fmaxf(v, __shfl_xor_sync(0xffffffffu, v, o));
    if ((threadIdx.x & 31) == 0) sh[threadIdx.x >> 5] = v;
    __syncthreads();
    if (threadIdx.x == 0) {
        float r = -1e30f;
        #pragma unroll
        for (int i = 0; i < 8; i++) r = fmaxf(r, sh[i]);
        sh[0] = r;
    }
    __syncthreads();
    float r = sh[0];
    __syncthreads();
    return r;
}

// ---------------- K1: QKV 1x1 conv = GEMM [768x256]x[256x1600] per batch ----------------
__global__ void k_qkv(const float* __restrict__ x, const float* __restrict__ w,
                      const float* __restrict__ bias) {
    __shared__ float ws[32][65];
    __shared__ float xs[32][64];
    int b = blockIdx.z;
    int oc0 = blockIdx.y * 64, p0 = blockIdx.x * 64;
    int tid = threadIdx.x, tx = tid & 15, ty = tid >> 4;
    float acc[4][4] = {};
    for (int k0 = 0; k0 < 256; k0 += 32) {
        #pragma unroll
        for (int l = 0; l < 8; l++) {
            int idx = tid + 256 * l;
            int r = idx >> 5, c = idx & 31;
            ws[c][r] = w[(oc0 + r) * 256 + k0 + c];
        }
        #pragma unroll
        for (int l = 0; l < 8; l++) {
            int idx = tid + 256 * l;
            int r = idx >> 6, c = idx & 63;
            xs[r][c] = x[(b * 256 + k0 + r) * NN + p0 + c];
        }
        __syncthreads();
        #pragma unroll
        for (int kk = 0; kk < 32; kk++) {
            float a[4], bv[4];
            #pragma unroll
            for (int i = 0; i < 4; i++) a[i] = ws[kk][ty * 4 + i];
            #pragma unroll
            for (int j = 0; j < 4; j++) bv[j] = xs[kk][tx * 4 + j];
            #pragma unroll
            for (int i = 0; i < 4; i++)
                #pragma unroll
                for (int j = 0; j < 4; j++) acc[i][j] += a[i] * bv[j];
        }
        __syncthreads();
    }
    #pragma unroll
    for (int i = 0; i < 4; i++) {
        int oc = oc0 + ty * 4 + i;
        float bv = bias[oc];
        #pragma unroll
        for (int j = 0; j < 4; j++)
            g_qkv0[(b * C3 + oc) * NN + p0 + tx * 4 + j] = acc[i][j] + bv;
    }
}

// ---------------- K2: depthwise 3x3, pad=1 ----------------
__global__ void k_dw(const float* __restrict__ pw, const float* __restrict__ pb) {
    int gid = blockIdx.x * 256 + threadIdx.x;
    if (gid >= BB * C3 * NN) return;
    int pix = gid % NN;
    int ch = (gid / NN) % C3;
    int b = gid / (NN * C3);
    int y = pix / 40, x = pix % 40;
    const float* src = g_qkv0 + (b * C3 + ch) * NN;
    const float* wp = pw + ch * 9;
    float s = pb[ch];
    #pragma unroll
    for (int ky = 0; ky < 3; ky++) {
        int yy = y + ky - 1;
        if (yy < 0 || yy >= 40) continue;
        #pragma unroll
        for (int kx = 0; kx < 3; kx++) {
            int xx = x + kx - 1;
            if (xx < 0 || xx >= 40) continue;
            s += wp[ky * 3 + kx] * src[yy * 40 + xx];
        }
    }
    g_qkv1[gid] = s;
}

// ---------------- K3: attn = scale * Q K^T, per (b,h), stored to g_attn ----------------
__global__ void k_qk() {
    __shared__ float qs[32][64];
    __shared__ float ks[32][64];
    int bh = blockIdx.z;
    int b = bh >> 3, h = bh & 7;
    int i0 = blockIdx.y * 64, j0 = blockIdx.x * 64;
    int tid = threadIdx.x, tx = tid & 15, ty = tid >> 4;
    const float* qp = g_qkv1 + (b * C3 + h * HD) * NN;
    const float* kp = g_qkv1 + (b * C3 + 256 + h * HD) * NN;
    #pragma unroll
    for (int l = 0; l < 8; l++) {
        int idx = tid + 256 * l;
        int r = idx >> 6, c = idx & 63;
        qs[r][c] = qp[r * NN + i0 + c];
        ks[r][c] = kp[r * NN + j0 + c];
    }
    __syncthreads();
    float acc[4][4] = {};
    #pragma unroll
    for (int d = 0; d < 32; d++) {
        float a[4], bv[4];
        #pragma unroll
        for (int i = 0; i < 4; i++) a[i] = qs[d][ty * 4 + i];
        #pragma unroll
        for (int j = 0; j < 4; j++) bv[j] = ks[d][tx * 4 + j];
        #pragma unroll
        for (int i = 0; i < 4; i++)
            #pragma unroll
            for (int j = 0; j < 4; j++) acc[i][j] += a[i] * bv[j];
    }
    float* out = g_attn + (size_t)bh * NN * NN;
    #pragma unroll
    for (int i = 0; i < 4; i++)
        #pragma unroll
        for (int j = 0; j < 4; j++)
            out[(size_t)(i0 + ty * 4 + i) * NN + j0 + tx * 4 + j] = acc[i][j] * SCALE;
}

// ---------------- K3b: per-row max + entropy (full softmax) ----------------
__global__ void k_stats() {
    int row = blockIdx.x;  // bh*1600 + i
    const float* a = g_attn + (size_t)row * NN;
    int tid = threadIdx.x;
    __shared__ float sh[8];
    float v[7];
    int cnt = 0;
    float m = -1e30f;
    for (int j = tid; j < NN; j += 256) {
        float f = a[j];
        v[cnt++] = f;
        m = fmaxf(m, f);
    }
    m = bmax(m, sh);
    float S = 0.f, T = 0.f;
    for (int t = 0; t < cnt; t++) {
        float e = expf(v[t] - m);
        S += e;
        T += v[t] * e;
    }
    S = bsum(S, sh);
    T = bsum(T, sh);
    if (tid == 0) {
        g_rowmax[row] = m;
        g_ent[row] = m + logf(S) - T / S;  // logZ - E_p[a]
    }
}

// ---------------- K4: entropy gate MLP -> keep per (b,h) ----------------
__global__ void k_gate(const float* __restrict__ g1w, const float* __restrict__ g1b,
                       const float* __restrict__ g2w, const float* __restrict__ g2b) {
    int bh = blockIdx.x;
    __shared__ float sh[8];
    float s = 0.f;
    for (int i = threadIdx.x; i < NN; i += 256) s += g_ent[bh * NN + i];
    s = bsum(s, sh);
    if (threadIdx.x == 0) {
        float e = s / (float)NN;
        float z = g2b[0];
        #pragma unroll
        for (int i = 0; i < 16; i++) {
            float hid = fmaxf(e * g1w[i] + g1b[i], 0.f);
            z += hid * g2w[i];
        }
        float ratio = 1.f / (1.f + expf(-z)) * 0.9f + 0.1f;
        int keep = (int)ceilf(ratio * (float)NN);
        keep = min(max(keep, 1), NN);
        g_keep[bh] = keep;
    }
}

// ---------------- K6a: radix-select kth largest + sparse softmax (in place) ----------------
__global__ void k_select() {
    int row = blockIdx.x;
    int bh = row / NN;
    int tid = threadIdx.x, wid = tid >> 5;
    float* a = g_attn + (size_t)row * NN;
    float v[7];
    int cnt = 0;
    for (int j = tid; j < NN; j += 256) v[cnt++] = a[j];

    __shared__ unsigned int hist[8][256];
    __shared__ unsigned int cum[256];
    __shared__ unsigned int s_b;
    __shared__ int s_rem;
    __shared__ float sh[8];

    int rem = g_keep[bh];
    unsigned int pref = 0;
    for (int r = 3; r >= 0; r--) {
        for (int i = tid; i < 2048; i += 256) ((unsigned int*)hist)[i] = 0u;
        __syncthreads();
        for (int t = 0; t < cnt; t++) {
            unsigned int key = f2key(v[t]);
            if (r == 3 || (key >> ((r + 1) * 8)) == pref)
                atomicAdd(&hist[wid][(key >> (r * 8)) & 0xFFu], 1u);
        }
        __syncthreads();
        unsigned int tot = 0;
        #pragma unroll
        for (int w = 0; w < 8; w++) tot += hist[w][tid];
        cum[tid] = tot;
        __syncthreads();
        // suffix sums: cum[t] = count of keys with byte >= t (within prefix)
        for (int off = 1; off < 256; off <<= 1) {
            unsigned int add = (tid + off < 256) ? cum[tid + off] : 0u;
            __syncthreads();
            cum[tid] += add;
            __syncthreads();
        }
        unsigned int mycum = cum[tid];
        unsigned int nxt = (tid == 255) ? 0u : cum[tid + 1];
        if (mycum >= (unsigned int)rem && nxt < (unsigned int)rem) {
            s_b = (unsigned int)tid;
            s_rem = rem - (int)nxt;
        }
        __syncthreads();
        pref = (pref << 8) | s_b;
        rem = s_rem;
        __syncthreads();
    }
    // pref is the exact key of the keep-th largest value
    float m = g_rowmax[row];
    bool kept[7];
    float S = 0.f;
    for (int t = 0; t < cnt; t++) {
        kept[t] = (f2key(v[t]) >= pref);
        if (kept[t]) S += expf(v[t] - m);
    }
    S = bsum(S, sh);
    float inv = 1.f / S;
    int j = tid;
    for (int t = 0; t < cnt; t++, j += 256)
        a[j] = kept[t] ? expf(v[t] - m) * inv : 0.f;
}

// ---------------- K6b: out = P @ V^T per (b,h), tiled ----------------
__global__ void k_pv() {
    __shared__ float ps[64][68];
    __shared__ float vs[64][33];
    int bh = blockIdx.y;
    int b = bh >> 3, h = bh & 7;
    int row0 = blockIdx.x * 64;
    int tid = threadIdx.x, w = tid >> 5, lane = tid & 31;
    const float* P = g_attn + (size_t)bh * NN * NN;
    const float* V = g_qkv1 + (b * C3 + 512 + h * HD) * NN;
    float acc[8] = {};
    for (int j0 = 0; j0 < NN; j0 += 64) {
        #pragma unroll
        for (int l = 0; l < 16; l++) {
            int idx = tid + 256 * l;
            int r = idx >> 6, c = idx & 63;
            ps[r][c] = P[(size_t)(row0 + r) * NN + j0 + c];
        }
        #pragma unroll
        for (int l = 0; l < 8; l++) {
            int idx = tid + 256 * l;
            int d = idx >> 6, c = idx & 63;
            vs[c][d] = V[d * NN + j0 + c];
        }
        __syncthreads();
        #pragma unroll
        for (int j = 0; j < 64; j += 4) {
            float v0 = vs[j][lane], v1 = vs[j + 1][lane];
            float v2 = vs[j + 2][lane], v3 = vs[j + 3][lane];
            #pragma unroll
            for (int rr = 0; rr < 8; rr++) {
                const float4 p4 = *(const float4*)&ps[w * 8 + rr][j];
                acc[rr] += p4.x * v0 + p4.y * v1 + p4.z * v2 + p4.w * v3;
            }
        }
        __syncthreads();
    }
    #pragma unroll
    for (int rr = 0; rr < 8; rr++)
        g_attout[(size_t)(b * NN + row0 + w * 8 + rr) * CC + h * HD + lane] = acc[rr];
}

// ---------------- K7: output projection + final transpose ----------------
__global__ void k_proj(const float* __restrict__ w, const float* __restrict__ bias,
                       float* __restrict__ out) {
    __shared__ float ws[32][65];
    __shared__ float as[32][65];
    int b = blockIdx.z;
    int co0 = blockIdx.y * 64, p0 = blockIdx.x * 64;
    int tid = threadIdx.x, tx = tid & 15, ty = tid >> 4;
    float acc[4][4] = {};
    for (int k0 = 0; k0 < 256; k0 += 32) {
        #pragma unroll
        for (int l = 0; l < 8; l++) {
            int idx = tid + 256 * l;
            int r = idx >> 5, c = idx & 31;
            ws[c][r] = w[(co0 + r) * 256 + k0 + c];
        }
        #pragma unroll
        for (int l = 0; l < 8; l++) {
            int idx = tid + 256 * l;
            int p = idx >> 5, c = idx & 31;
            as[c][p] = g_attout[(size_t)(b * NN + p0 + p) * CC + k0 + c];
        }
        __syncthreads();
        #pragma unroll
        for (int kk = 0; kk < 32; kk++) {
            float a[4], bv[4];
            #pragma unroll
            for (int i = 0; i < 4; i++) a[i] = ws[kk][ty * 4 + i];
            #pragma unroll
            for (int j = 0; j < 4; j++) bv[j] = as[kk][tx * 4 + j];
            #pragma unroll
            for (int i = 0; i < 4; i++)
                #pragma unroll
                for (int j = 0; j < 4; j++) acc[i][j] += a[i] * bv[j];
        }
        __syncthreads();
    }
    #pragma unroll
    for (int i = 0; i < 4; i++) {
        int co = co0 + ty * 4 + i;
        float bv = bias[co];
        #pragma unroll
        for (int j = 0; j < 4; j++)
            out[(b * CC + co) * NN + p0 + tx * 4 + j] = acc[i][j] + bv;
    }
}

extern "C" void kernel_launch(void* const* d_in, const int* in_sizes, int n_in,
                              void* d_out, int out_size) {
    const float* x      = (const float*)d_in[0];
    const float* qkv_w  = (const float*)d_in[1];
    const float* qkv_b  = (const float*)d_in[2];
    const float* pos_w  = (const float*)d_in[3];
    const float* pos_b  = (const float*)d_in[4];
    const float* proj_w = (const float*)d_in[5];
    const float* proj_b = (const float*)d_in[6];
    const float* g1w    = (const float*)d_in[7];
    const float* g1b    = (const float*)d_in[8];
    const float* g2w    = (const float*)d_in[9];
    const float* g2b    = (const float*)d_in[10];
    float* out = (float*)d_out;

    k_qkv<<<dim3(25, 12, 2), 256>>>(x, qkv_w, qkv_b);
    k_dw<<<(BB * C3 * NN + 255) / 256, 256>>>(pos_w, pos_b);
    k_qk<<<dim3(25, 25, 16), 256>>>();
    k_stats<<<BH * NN, 256>>>();
    k_gate<<<BH, 256>>>(g1w, g1b, g2w, g2b);
    k_select<<<BH * NN, 256>>>();
    k_pv<<<dim3(25, 16), 256>>>();
    k_proj<<<dim3(25, 4, 2), 256>>>(proj_w, proj_b, out);
}

// round 2
// speedup vs baseline: 1.0590x; 1.0590x over previous
#include <cuda_runtime.h>
#include <math.h>

#define BB 2
#define CC 256
#define NHEADS 8
#define HD 32
#define NN 1600
#define C3 768
#define BH 16
#define SCALE 0.17677669529663687f  // 1/sqrt(32)

// ---------------- scratch (static device memory; no allocations) ----------------
__device__ float g_qkv0[BB * C3 * NN];             // after 1x1 conv
__device__ float g_qkv1[BB * C3 * NN];             // after depthwise 3x3
__device__ float g_attn[(size_t)BH * NN * NN];     // 163.84 MB raw logits (never rewritten)
__device__ float g_S[BH * NN];                     // per-row sum exp(a)
__device__ float g_T[BH * NN];                     // per-row sum a*exp(a)
__device__ unsigned int g_pref[BH * NN];           // per-row kth-largest key
__device__ float g_inv[BH * NN];                   // per-row 1/sum_kept exp(a)
__device__ int   g_keep[BH];
__device__ float g_attout[BB * NN * CC];           // [b][pixel][c] pre-projection

// ---------------- helpers ----------------
__device__ __forceinline__ unsigned int f2key(float f) {
    unsigned int u = __float_as_uint(f);
    return (u & 0x80000000u) ? ~u : (u | 0x80000000u);
}

__device__ __forceinline__ float bsum(float v, volatile float* sh) {
    #pragma unroll
    for (int o = 16; o; o >>= 1) v += __shfl_xor_sync(0xffffffffu, v, o);
    if ((threadIdx.x & 31) == 0) sh[threadIdx.x >> 5] = v;
    __syncthreads();
    if (threadIdx.x == 0) {
        float r = 0.f;
        #pragma unroll
        for (int i = 0; i < 8; i++) r += sh[i];
        sh[0] = r;
    }
    __syncthreads();
    float r = sh[0];
    __syncthreads();
    return r;
}

// ---------------- K0: zero the stat accumulators ----------------
__global__ void k_zero() {
    int i = blockIdx.x * 256 + threadIdx.x;
    if (i < BH * NN) { g_S[i] = 0.f; g_T[i] = 0.f; }
}

// ---------------- K1: QKV 1x1 conv = GEMM [768x256]x[256x1600] per batch ----------------
__global__ void k_qkv(const float* __restrict__ x, const float* __restrict__ w,
                      const float* __restrict__ bias) {
    __shared__ float ws[32][65];
    __shared__ float xs[32][64];
    int b = blockIdx.z;
    int oc0 = blockIdx.y * 64, p0 = blockIdx.x * 64;
    int tid = threadIdx.x, tx = tid & 15, ty = tid >> 4;
    float acc[4][4] = {};
    for (int k0 = 0; k0 < 256; k0 += 32) {
        #pragma unroll
        for (int l = 0; l < 8; l++) {
            int idx = tid + 256 * l;
            int r = idx >> 5, c = idx & 31;
            ws[c][r] = w[(oc0 + r) * 256 + k0 + c];
        }
        #pragma unroll
        for (int l = 0; l < 8; l++) {
            int idx = tid + 256 * l;
            int r = idx >> 6, c = idx & 63;
            xs[r][c] = x[(b * 256 + k0 + r) * NN + p0 + c];
        }
        __syncthreads();
        #pragma unroll
        for (int kk = 0; kk < 32; kk++) {
            float a[4], bv[4];
            #pragma unroll
            for (int i = 0; i < 4; i++) a[i] = ws[kk][ty * 4 + i];
            #pragma unroll
            for (int j = 0; j < 4; j++) bv[j] = xs[kk][tx * 4 + j];
            #pragma unroll
            for (int i = 0; i < 4; i++)
                #pragma unroll
                for (int j = 0; j < 4; j++) acc[i][j] += a[i] * bv[j];
        }
        __syncthreads();
    }
    #pragma unroll
    for (int i = 0; i < 4; i++) {
        int oc = oc0 + ty * 4 + i;
        float bv = bias[oc];
        #pragma unroll
        for (int j = 0; j < 4; j++)
            g_qkv0[(b * C3 + oc) * NN + p0 + tx * 4 + j] = acc[i][j] + bv;
    }
}

// ---------------- K2: depthwise 3x3, pad=1 ----------------
__global__ void k_dw(const float* __restrict__ pw, const float* __restrict__ pb) {
    int gid = blockIdx.x * 256 + threadIdx.x;
    if (gid >= BB * C3 * NN) return;
    int pix = gid % NN;
    int ch = (gid / NN) % C3;
    int b = gid / (NN * C3);
    int y = pix / 40, x = pix % 40;
    const float* src = g_qkv0 + (b * C3 + ch) * NN;
    const float* wp = pw + ch * 9;
    float s = pb[ch];
    #pragma unroll
    for (int ky = 0; ky < 3; ky++) {
        int yy = y + ky - 1;
        if (yy < 0 || yy >= 40) continue;
        #pragma unroll
        for (int kx = 0; kx < 3; kx++) {
            int xx = x + kx - 1;
            if (xx < 0 || xx >= 40) continue;
            s += wp[ky * 3 + kx] * src[yy * 40 + xx];
        }
    }
    g_qkv1[gid] = s;
}

// ---------------- K3: attn = scale*QK^T + fused entropy stat accumulation ----------------
__global__ void k_qk() {
    __shared__ float qs[32][64];
    __shared__ float ks[32][64];
    int bh = blockIdx.z;
    int b = bh >> 3, h = bh & 7;
    int i0 = blockIdx.y * 64, j0 = blockIdx.x * 64;
    int tid = threadIdx.x, tx = tid & 15, ty = tid >> 4;
    const float* qp = g_qkv1 + (b * C3 + h * HD) * NN;
    const float* kp = g_qkv1 + (b * C3 + 256 + h * HD) * NN;
    #pragma unroll
    for (int l = 0; l < 8; l++) {
        int idx = tid + 256 * l;
        int r = idx >> 6, c = idx & 63;
        qs[r][c] = qp[r * NN + i0 + c];
        ks[r][c] = kp[r * NN + j0 + c];
    }
    __syncthreads();
    float acc[4][4] = {};
    #pragma unroll
    for (int d = 0; d < 32; d++) {
        float a[4], bv[4];
        #pragma unroll
        for (int i = 0; i < 4; i++) a[i] = qs[d][ty * 4 + i];
        #pragma unroll
        for (int j = 0; j < 4; j++) bv[j] = ks[d][tx * 4 + j];
        #pragma unroll
        for (int i = 0; i < 4; i++)
            #pragma unroll
            for (int j = 0; j < 4; j++) acc[i][j] += a[i] * bv[j];
    }
    float* out = g_attn + (size_t)bh * NN * NN;
    #pragma unroll
    for (int i = 0; i < 4; i++) {
        int row = i0 + ty * 4 + i;
        float se = 0.f, te = 0.f;
        #pragma unroll
        for (int j = 0; j < 4; j++) {
            float a = acc[i][j] * SCALE;
            out[(size_t)row * NN + j0 + tx * 4 + j] = a;
            float e = expf(a);
            se += e;
            te += a * e;
        }
        // reduce over the 16 tx lanes of this row (lanes 0-15 / 16-31 in warp)
        #pragma unroll
        for (int o = 8; o; o >>= 1) {
            se += __shfl_xor_sync(0xffffffffu, se, o);
            te += __shfl_xor_sync(0xffffffffu, te, o);
        }
        if (tx == 0) {
            atomicAdd(&g_S[bh * NN + row], se);
            atomicAdd(&g_T[bh * NN + row], te);
        }
    }
}

// ---------------- K4: entropy gate MLP -> keep per (b,h) ----------------
__global__ void k_gate(const float* __restrict__ g1w, const float* __restrict__ g1b,
                       const float* __restrict__ g2w, const float* __restrict__ g2b) {
    int bh = blockIdx.x;
    __shared__ float sh[8];
    float s = 0.f;
    for (int i = threadIdx.x; i < NN; i += 256) {
        float S = g_S[bh * NN + i];
        float T = g_T[bh * NN + i];
        s += logf(S) - T / S;
    }
    s = bsum(s, sh);
    if (threadIdx.x == 0) {
        float e = s / (float)NN;
        float z = g2b[0];
        #pragma unroll
        for (int i = 0; i < 16; i++) {
            float hid = fmaxf(e * g1w[i] + g1b[i], 0.f);
            z += hid * g2w[i];
        }
        float ratio = 1.f / (1.f + expf(-z)) * 0.9f + 0.1f;
        int keep = (int)ceilf(ratio * (float)NN);
        keep = min(max(keep, 1), NN);
        g_keep[bh] = keep;
    }
}

// ---------------- K5: radix-select kth largest -> per-row threshold + inv ----------------
__global__ void k_select() {
    int row = blockIdx.x;
    int bh = row / NN;
    int tid = threadIdx.x, wid = tid >> 5;
    const float* a = g_attn + (size_t)row * NN;
    float v[7];
    int cnt = 0;
    for (int j = tid; j < NN; j += 256) v[cnt++] = a[j];

    __shared__ unsigned int hist[8][256];
    __shared__ unsigned int cum[256];
    __shared__ unsigned int s_b;
    __shared__ int s_rem;
    __shared__ float sh[8];

    int rem = g_keep[bh];
    unsigned int pref = 0;
    for (int r = 3; r >= 0; r--) {
        for (int i = tid; i < 2048; i += 256) ((unsigned int*)hist)[i] = 0u;
        __syncthreads();
        for (int t = 0; t < cnt; t++) {
            unsigned int key = f2key(v[t]);
            if (r == 3 || (key >> ((r + 1) * 8)) == pref)
                atomicAdd(&hist[wid][(key >> (r * 8)) & 0xFFu], 1u);
        }
        __syncthreads();
        unsigned int tot = 0;
        #pragma unroll
        for (int w = 0; w < 8; w++) tot += hist[w][tid];
        cum[tid] = tot;
        __syncthreads();
        for (int off = 1; off < 256; off <<= 1) {
            unsigned int add = (tid + off < 256) ? cum[tid + off] : 0u;
            __syncthreads();
            cum[tid] += add;
            __syncthreads();
        }
        unsigned int mycum = cum[tid];
        unsigned int nxt = (tid == 255) ? 0u : cum[tid + 1];
        if (mycum >= (unsigned int)rem && nxt < (unsigned int)rem) {
            s_b = (unsigned int)tid;
            s_rem = rem - (int)nxt;
        }
        __syncthreads();
        pref = (pref << 8) | s_b;
        rem = s_rem;
        __syncthreads();
    }
    // pref = exact key of the keep-th largest value; sum exp over kept
    float S = 0.f;
    for (int t = 0; t < cnt; t++)
        if (f2key(v[t]) >= pref) S += expf(v[t]);
    S = bsum(S, sh);
    if (tid == 0) {
        g_pref[row] = pref;
        g_inv[row] = 1.f / S;
    }
}

// ---------------- K6: out = P @ V^T per (b,h), P computed on the fly ----------------
__global__ void k_pv() {
    __shared__ float ps[64][68];
    __shared__ float vs[64][33];
    __shared__ unsigned int pf[64];
    __shared__ float iv[64];
    int bh = blockIdx.y;
    int b = bh >> 3, h = bh & 7;
    int row0 = blockIdx.x * 64;
    int tid = threadIdx.x, w = tid >> 5, lane = tid & 31;
    const float* P = g_attn + (size_t)bh * NN * NN;
    const float* V = g_qkv1 + (b * C3 + 512 + h * HD) * NN;
    if (tid < 64) {
        pf[tid] = g_pref[bh * NN + row0 + tid];
        iv[tid] = g_inv[bh * NN + row0 + tid];
    }
    __syncthreads();
    float acc[8] = {};
    for (int j0 = 0; j0 < NN; j0 += 64) {
        #pragma unroll
        for (int l = 0; l < 16; l++) {
            int idx = tid + 256 * l;
            int r = idx >> 6, c = idx & 63;
            float a = P[(size_t)(row0 + r) * NN + j0 + c];
            float p = 0.f;
            if (f2key(a) >= pf[r]) p = expf(a) * iv[r];
            ps[r][c] = p;
        }
        #pragma unroll
        for (int l = 0; l < 8; l++) {
            int idx = tid + 256 * l;
            int d = idx >> 6, c = idx & 63;
            vs[c][d] = V[d * NN + j0 + c];
        }
        __syncthreads();
        #pragma unroll
        for (int j = 0; j < 64; j += 4) {
            float v0 = vs[j][lane], v1 = vs[j + 1][lane];
            float v2 = vs[j + 2][lane], v3 = vs[j + 3][lane];
            #pragma unroll
            for (int rr = 0; rr < 8; rr++) {
                const float4 p4 = *(const float4*)&ps[w * 8 + rr][j];
                acc[rr] += p4.x * v0 + p4.y * v1 + p4.z * v2 + p4.w * v3;
            }
        }
        __syncthreads();
    }
    #pragma unroll
    for (int rr = 0; rr < 8; rr++)
        g_attout[(size_t)(b * NN + row0 + w * 8 + rr) * CC + h * HD + lane] = acc[rr];
}

// ---------------- K7: output projection + final transpose ----------------
__global__ void k_proj(const float* __restrict__ w, const float* __restrict__ bias,
                       float* __restrict__ out) {
    __shared__ float ws[32][65];
    __shared__ float as[32][65];
    int b = blockIdx.z;
    int co0 = blockIdx.y * 64, p0 = blockIdx.x * 64;
    int tid = threadIdx.x, tx = tid & 15, ty = tid >> 4;
    float acc[4][4] = {};
    for (int k0 = 0; k0 < 256; k0 += 32) {
        #pragma unroll
        for (int l = 0; l < 8; l++) {
            int idx = tid + 256 * l;
            int r = idx >> 5, c = idx & 31;
            ws[c][r] = w[(co0 + r) * 256 + k0 + c];
        }
        #pragma unroll
        for (int l = 0; l < 8; l++) {
            int idx = tid + 256 * l;
            int p = idx >> 5, c = idx & 31;
            as[c][p] = g_attout[(size_t)(b * NN + p0 + p) * CC + k0 + c];
        }
        __syncthreads();
        #pragma unroll
        for (int kk = 0; kk < 32; kk++) {
            float a[4], bv[4];
            #pragma unroll
            for (int i = 0; i < 4; i++) a[i] = ws[kk][ty * 4 + i];
            #pragma unroll
            for (int j = 0; j < 4; j++) bv[j] = as[kk][tx * 4 + j];
            #pragma unroll
            for (int i = 0; i < 4; i++)
                #pragma unroll
                for (int j = 0; j < 4; j++) acc[i][j] += a[i] * bv[j];
        }
        __syncthreads();
    }
    #pragma unroll
    for (int i = 0; i < 4; i++) {
        int co = co0 + ty * 4 + i;
        float bv = bias[co];
        #pragma unroll
        for (int j = 0; j < 4; j++)
            out[(b * CC + co) * NN + p0 + tx * 4 + j] = acc[i][j] + bv;
    }
}

extern "C" void kernel_launch(void* const* d_in, const int* in_sizes, int n_in,
                              void* d_out, int out_size) {
    const float* x      = (const float*)d_in[0];
    const float* qkv_w  = (const float*)d_in[1];
    const float* qkv_b  = (const float*)d_in[2];
    const float* pos_w  = (const float*)d_in[3];
    const float* pos_b  = (const float*)d_in[4];
    const float* proj_w = (const float*)d_in[5];
    const float* proj_b = (const float*)d_in[6];
    const float* g1w    = (const float*)d_in[7];
    const float* g1b    = (const float*)d_in[8];
    const float* g2w    = (const float*)d_in[9];
    const float* g2b    = (const float*)d_in[10];
    float* out = (float*)d_out;

    k_zero<<<(BH * NN + 255) / 256, 256>>>();
    k_qkv<<<dim3(25, 12, 2), 256>>>(x, qkv_w, qkv_b);
    k_dw<<<(BB * C3 * NN + 255) / 256, 256>>>(pos_w, pos_b);
    k_qk<<<dim3(25, 25, 16), 256>>>();
    k_gate<<<BH, 256>>>(g1w, g1b, g2w, g2b);
    k_select<<<BH * NN, 256>>>();
    k_pv<<<dim3(25, 16), 256>>>();
    k_proj<<<dim3(25, 4, 2), 256>>>(proj_w, proj_b, out);
}

// round 3
// speedup vs baseline: 1.3961x; 1.3183x over previous
#include <cuda_runtime.h>
#include <math.h>

#define BB 2
#define CC 256
#define NHEADS 8
#define HD 32
#define NN 1600
#define C3 768
#define BH 16
#define SCALE 0.17677669529663687f  // 1/sqrt(32)

// ---------------- scratch (static device memory; no allocations) ----------------
__device__ float g_qkv0[BB * C3 * NN];
__device__ float g_qkv1[BB * C3 * NN];
__device__ float g_attn[(size_t)BH * NN * NN];     // raw logits, never rewritten
__device__ float g_S[BH * NN];
__device__ float g_T[BH * NN];
__device__ unsigned int g_pref[BH * NN];
__device__ float g_inv[BH * NN];
__device__ int   g_keep[BH];
__device__ float g_attout[BB * NN * CC];

// ---------------- helpers ----------------
__device__ __forceinline__ unsigned int f2key(float f) {
    unsigned int u = __float_as_uint(f);
    return (u & 0x80000000u) ? ~u : (u | 0x80000000u);
}

__device__ __forceinline__ float bsum(float v, volatile float* sh) {
    #pragma unroll
    for (int o = 16; o; o >>= 1) v += __shfl_xor_sync(0xffffffffu, v, o);
    if ((threadIdx.x & 31) == 0) sh[threadIdx.x >> 5] = v;
    __syncthreads();
    if (threadIdx.x == 0) {
        float r = 0.f;
        #pragma unroll
        for (int i = 0; i < 8; i++) r += sh[i];
        sh[0] = r;
    }
    __syncthreads();
    float r = sh[0];
    __syncthreads();
    return r;
}

// ---------------- K0: zero stat accumulators ----------------
__global__ void k_zero() {
    int i = blockIdx.x * 256 + threadIdx.x;
    if (i < BH * NN) { g_S[i] = 0.f; g_T[i] = 0.f; }
}

// ---------------- K1: QKV 1x1 conv, 128x128 tile, 8x8/thread ----------------
__global__ __launch_bounds__(256, 2) void k_qkv(const float* __restrict__ x,
                                                const float* __restrict__ w,
                                                const float* __restrict__ bias) {
    __shared__ float ws[128][33];   // [oc][k]
    __shared__ float xs[32][128];   // [k][pixel]
    int b = blockIdx.z;
    int oc0 = blockIdx.y * 128, p0 = blockIdx.x * 128;
    int tid = threadIdx.x, tx = tid & 15, ty = tid >> 4;
    float acc[8][8] = {};
    for (int k0 = 0; k0 < 256; k0 += 32) {
        #pragma unroll
        for (int l = 0; l < 4; l++) {
            int f = tid + 256 * l;          // 0..1023 float4 over w tile
            int oc = f >> 3, k4 = f & 7;
            float4 v = *(const float4*)&w[(oc0 + oc) * 256 + k0 + k4 * 4];
            ws[oc][k4 * 4 + 0] = v.x; ws[oc][k4 * 4 + 1] = v.y;
            ws[oc][k4 * 4 + 2] = v.z; ws[oc][k4 * 4 + 3] = v.w;
        }
        #pragma unroll
        for (int l = 0; l < 4; l++) {
            int f = tid + 256 * l;
            int d = f >> 5, c4 = f & 31;
            int col = p0 + c4 * 4;
            float4 v = make_float4(0.f, 0.f, 0.f, 0.f);
            if (col < NN) v = *(const float4*)&x[(b * 256 + k0 + d) * NN + col];
            *(float4*)&xs[d][c4 * 4] = v;
        }
        __syncthreads();
        #pragma unroll
        for (int d = 0; d < 32; d++) {
            float a[8], bv[8];
            #pragma unroll
            for (int i = 0; i < 8; i++) a[i] = ws[ty * 8 + i][d];
            *(float4*)&bv[0] = *(float4*)&xs[d][tx * 8];
            *(float4*)&bv[4] = *(float4*)&xs[d][tx * 8 + 4];
            #pragma unroll
            for (int i = 0; i < 8; i++)
                #pragma unroll
                for (int j = 0; j < 8; j++) acc[i][j] += a[i] * bv[j];
        }
        __syncthreads();
    }
    int col0 = p0 + tx * 8;
    if (col0 < NN) {
        #pragma unroll
        for (int i = 0; i < 8; i++) {
            int oc = oc0 + ty * 8 + i;
            float bv = bias[oc];
            float o[8];
            #pragma unroll
            for (int j = 0; j < 8; j++) o[j] = acc[i][j] + bv;
            *(float4*)&g_qkv0[(b * C3 + oc) * NN + col0]     = *(float4*)&o[0];
            *(float4*)&g_qkv0[(b * C3 + oc) * NN + col0 + 4] = *(float4*)&o[4];
        }
    }
}

// ---------------- K2: depthwise 3x3, pad=1 ----------------
__global__ void k_dw(const float* __restrict__ pw, const float* __restrict__ pb) {
    int gid = blockIdx.x * 256 + threadIdx.x;
    if (gid >= BB * C3 * NN) return;
    int pix = gid % NN;
    int ch = (gid / NN) % C3;
    int b = gid / (NN * C3);
    int y = pix / 40, x = pix % 40;
    const float* src = g_qkv0 + (b * C3 + ch) * NN;
    const float* wp = pw + ch * 9;
    float s = pb[ch];
    #pragma unroll
    for (int ky = 0; ky < 3; ky++) {
        int yy = y + ky - 1;
        if (yy < 0 || yy >= 40) continue;
        #pragma unroll
        for (int kx = 0; kx < 3; kx++) {
            int xx = x + kx - 1;
            if (xx < 0 || xx >= 40) continue;
            s += wp[ky * 3 + kx] * src[yy * 40 + xx];
        }
    }
    g_qkv1[gid] = s;
}

// ---------------- K3: attn = scale*QK^T, 128x128 tile, 8x8/thread + fused stats ----------------
__global__ __launch_bounds__(256, 2) void k_qk() {
    __shared__ float qs[32][128];
    __shared__ float ks[32][128];
    int bh = blockIdx.z;
    int b = bh >> 3, h = bh & 7;
    int i0 = blockIdx.y * 128, j0 = blockIdx.x * 128;
    int tid = threadIdx.x, tx = tid & 15, ty = tid >> 4;
    const float* qp = g_qkv1 + (b * C3 + h * HD) * NN;
    const float* kp = g_qkv1 + (b * C3 + 256 + h * HD) * NN;
    #pragma unroll
    for (int l = 0; l < 4; l++) {
        int f = tid + 256 * l;
        int d = f >> 5, c4 = f & 31;
        int ci = i0 + c4 * 4, cj = j0 + c4 * 4;
        float4 vq = make_float4(0.f, 0.f, 0.f, 0.f);
        float4 vk = make_float4(0.f, 0.f, 0.f, 0.f);
        if (ci < NN) vq = *(const float4*)&qp[d * NN + ci];
        if (cj < NN) vk = *(const float4*)&kp[d * NN + cj];
        *(float4*)&qs[d][c4 * 4] = vq;
        *(float4*)&ks[d][c4 * 4] = vk;
    }
    __syncthreads();
    float acc[8][8] = {};
    #pragma unroll
    for (int d = 0; d < 32; d++) {
        float a[8], bv[8];
        *(float4*)&a[0]  = *(float4*)&qs[d][ty * 8];
        *(float4*)&a[4]  = *(float4*)&qs[d][ty * 8 + 4];
        *(float4*)&bv[0] = *(float4*)&ks[d][tx * 8];
        *(float4*)&bv[4] = *(float4*)&ks[d][tx * 8 + 4];
        #pragma unroll
        for (int i = 0; i < 8; i++)
            #pragma unroll
            for (int j = 0; j < 8; j++) acc[i][j] += a[i] * bv[j];
    }
    float* outp = g_attn + (size_t)bh * NN * NN;
    int col0 = j0 + tx * 8;
    bool colok = (col0 < NN);
    #pragma unroll
    for (int i = 0; i < 8; i++) {
        int rowi = i0 + ty * 8 + i;
        if (rowi >= NN) continue;               // uniform across the 16-lane group
        float av[8];
        #pragma unroll
        for (int j = 0; j < 8; j++) av[j] = acc[i][j] * SCALE;
        if (colok) {
            *(float4*)&outp[(size_t)rowi * NN + col0]     = *(float4*)&av[0];
            *(float4*)&outp[(size_t)rowi * NN + col0 + 4] = *(float4*)&av[4];
        }
        float se = 0.f, te = 0.f;
        if (colok) {
            #pragma unroll
            for (int j = 0; j < 8; j++) {
                float e = expf(av[j]);
                se += e;
                te += av[j] * e;
            }
        }
        #pragma unroll
        for (int o = 8; o; o >>= 1) {
            se += __shfl_xor_sync(0xffffffffu, se, o);
            te += __shfl_xor_sync(0xffffffffu, te, o);
        }
        if (tx == 0) {
            atomicAdd(&g_S[bh * NN + rowi], se);
            atomicAdd(&g_T[bh * NN + rowi], te);
        }
    }
}

// ---------------- K4: entropy gate MLP -> keep per (b,h) ----------------
__global__ void k_gate(const float* __restrict__ g1w, const float* __restrict__ g1b,
                       const float* __restrict__ g2w, const float* __restrict__ g2b) {
    int bh = blockIdx.x;
    __shared__ float sh[8];
    float s = 0.f;
    for (int i = threadIdx.x; i < NN; i += 256) {
        float S = g_S[bh * NN + i];
        float T = g_T[bh * NN + i];
        s += logf(S) - T / S;
    }
    s = bsum(s, sh);
    if (threadIdx.x == 0) {
        float e = s / (float)NN;
        float z = g2b[0];
        #pragma unroll
        for (int i = 0; i < 16; i++) {
            float hid = fmaxf(e * g1w[i] + g1b[i], 0.f);
            z += hid * g2w[i];
        }
        float ratio = 1.f / (1.f + expf(-z)) * 0.9f + 0.1f;
        int keep = (int)ceilf(ratio * (float)NN);
        keep = min(max(keep, 1), NN);
        g_keep[bh] = keep;
    }
}

// ---------------- K5: warp-per-row radix select (no block barriers) ----------------
__global__ __launch_bounds__(128) void k_select() {
    __shared__ float rowv[4][NN];
    __shared__ unsigned int hist[4][256];
    int w = threadIdx.x >> 5, lane = threadIdx.x & 31;
    int row = blockIdx.x * 4 + w;
    int bh = row / NN;
    const float* a = g_attn + (size_t)row * NN;
    float* rv = rowv[w];
    unsigned int* hh = hist[w];
    // load row (coalesced float4 per warp)
    for (int t = lane; t < NN / 4; t += 32)
        ((float4*)rv)[t] = ((const float4*)a)[t];
    __syncwarp();
    int rem = g_keep[bh];
    unsigned int pref = 0;
    #pragma unroll
    for (int r = 3; r >= 0; r--) {
        ((uint4*)hh)[lane]      = make_uint4(0u, 0u, 0u, 0u);
        ((uint4*)hh)[lane + 32] = make_uint4(0u, 0u, 0u, 0u);
        __syncwarp();
        for (int t = 0; t < NN / 32; t++) {
            unsigned int key = f2key(rv[t * 32 + lane]);
            bool part = (r == 3) || ((key >> ((r + 1) * 8)) == pref);
            if (part) atomicAdd(&hh[(key >> (r * 8)) & 0xFFu], 1u);
        }
        __syncwarp();
        // lane owns bins [lane*8, lane*8+8)
        unsigned int bins[8], loc[8];
        #pragma unroll
        for (int k = 0; k < 8; k++) bins[k] = hh[lane * 8 + k];
        loc[7] = bins[7];
        #pragma unroll
        for (int k = 6; k >= 0; k--) loc[k] = loc[k + 1] + bins[k];
        unsigned int lsum = loc[0];
        unsigned int v = lsum;
        #pragma unroll
        for (int off = 1; off < 32; off <<= 1) {
            unsigned int o = __shfl_down_sync(0xffffffffu, v, off);
            if (lane + off < 32) v += o;
        }
        unsigned int above = v - lsum;   // sum over lanes > lane (higher bins)
        int foundk = -1;
        int newrem = 0;
        #pragma unroll
        for (int k = 0; k < 8; k++) {
            unsigned int cum = loc[k] + above;
            unsigned int cumn = ((k < 7) ? loc[k + 1] : 0u) + above;
            if (cum >= (unsigned int)rem && cumn < (unsigned int)rem) {
                foundk = k;
                newrem = rem - (int)cumn;
            }
        }
        unsigned int ball = __ballot_sync(0xffffffffu, foundk >= 0);
        int src = __ffs(ball) - 1;
        int bb = __shfl_sync(0xffffffffu, lane * 8 + foundk, src);
        rem = __shfl_sync(0xffffffffu, newrem, src);
        pref = (pref << 8) | (unsigned int)bb;
        __syncwarp();
    }
    // kept-sum of exp
    float S = 0.f;
    for (int t = 0; t < NN / 32; t++) {
        float vv = rv[t * 32 + lane];
        if (f2key(vv) >= pref) S += expf(vv);
    }
    #pragma unroll
    for (int o = 16; o; o >>= 1) S += __shfl_xor_sync(0xffffffffu, S, o);
    if (lane == 0) {
        g_pref[row] = pref;
        g_inv[row] = 1.f / S;
    }
}

// ---------------- K6: out = P @ V^T, 64x32 block, 4x4/thread, P on the fly ----------------
__global__ __launch_bounds__(128) void k_pv() {
    __shared__ float ps[64][68];        // [row][jj]
    __shared__ float vs[64][33];        // [jj][c] (scalar access only)
    __shared__ unsigned int pf[64];
    __shared__ float iv[64];
    int bh = blockIdx.y;
    int b = bh >> 3, h = bh & 7;
    int row0 = blockIdx.x * 64;
    int tid = threadIdx.x, tx = tid & 7, ty = tid >> 3;   // tx: col grp, ty: row grp
    const float* A = g_attn + (size_t)bh * NN * NN;
    const float* V = g_qkv1 + (b * C3 + 512 + h * HD) * NN;
    if (tid < 64) {
        pf[tid] = g_pref[bh * NN + row0 + tid];
        iv[tid] = g_inv[bh * NN + row0 + tid];
    }
    __syncthreads();
    float acc[4][4] = {};
    for (int j0 = 0; j0 < NN; j0 += 64) {
        #pragma unroll
        for (int l = 0; l < 8; l++) {
            int f = tid + 128 * l;            // 0..1023 float4 of P tile
            int rr = f >> 4, c4 = f & 15;
            float4 vv = *(const float4*)&A[(size_t)(row0 + rr) * NN + j0 + c4 * 4];
            unsigned int pk = pf[rr];
            float ivv = iv[rr];
            float4 pp;
            pp.x = (f2key(vv.x) >= pk) ? expf(vv.x) * ivv : 0.f;
            pp.y = (f2key(vv.y) >= pk) ? expf(vv.y) * ivv : 0.f;
            pp.z = (f2key(vv.z) >= pk) ? expf(vv.z) * ivv : 0.f;
            pp.w = (f2key(vv.w) >= pk) ? expf(vv.w) * ivv : 0.f;
            *(float4*)&ps[rr][c4 * 4] = pp;
        }
        #pragma unroll
        for (int l = 0; l < 4; l++) {
            int f = tid + 128 * l;            // 0..511 float4 of V tile
            int c = f >> 4, j4 = f & 15;
            float4 vv = *(const float4*)&V[c * NN + j0 + j4 * 4];
            vs[j4 * 4 + 0][c] = vv.x;
            vs[j4 * 4 + 1][c] = vv.y;
            vs[j4 * 4 + 2][c] = vv.z;
            vs[j4 * 4 + 3][c] = vv.w;
        }
        __syncthreads();
        #pragma unroll
        for (int jj = 0; jj < 64; jj += 4) {
            float pr[4][4];
            #pragma unroll
            for (int r = 0; r < 4; r++)
                *(float4*)pr[r] = *(float4*)&ps[ty * 4 + r][jj];
            float vr[4][4];
            #pragma unroll
            for (int k = 0; k < 4; k++)
                #pragma unroll
                for (int c = 0; c < 4; c++) vr[k][c] = vs[jj + k][tx * 4 + c];
            #pragma unroll
            for (int r = 0; r < 4; r++)
                #pragma unroll
                for (int k = 0; k < 4; k++)
                    #pragma unroll
                    for (int c = 0; c < 4; c++) acc[r][c] += pr[r][k] * vr[k][c];
        }
        __syncthreads();
    }
    #pragma unroll
    for (int r = 0; r < 4; r++)
        *(float4*)&g_attout[(size_t)(b * NN + row0 + ty * 4 + r) * CC + h * HD + tx * 4]
            = *(float4*)acc[r];
}

// ---------------- K7: output projection + final transpose ----------------
__global__ void k_proj(const float* __restrict__ w, const float* __restrict__ bias,
                       float* __restrict__ out) {
    __shared__ float ws[32][65];
    __shared__ float as[32][65];
    int b = blockIdx.z;
    int co0 = blockIdx.y * 64, p0 = blockIdx.x * 64;
    int tid = threadIdx.x, tx = tid & 15, ty = tid >> 4;
    float acc[4][4] = {};
    for (int k0 = 0; k0 < 256; k0 += 32) {
        #pragma unroll
        for (int l = 0; l < 8; l++) {
            int idx = tid + 256 * l;
            int r = idx >> 5, c = idx & 31;
            ws[c][r] = w[(co0 + r) * 256 + k0 + c];
        }
        #pragma unroll
        for (int l = 0; l < 8; l++) {
            int idx = tid + 256 * l;
            int p = idx >> 5, c = idx & 31;
            as[c][p] = g_attout[(size_t)(b * NN + p0 + p) * CC + k0 + c];
        }
        __syncthreads();
        #pragma unroll
        for (int kk = 0; kk < 32; kk++) {
            float a[4], bv[4];
            #pragma unroll
            for (int i = 0; i < 4; i++) a[i] = ws[kk][ty * 4 + i];
            #pragma unroll
            for (int j = 0; j < 4; j++) bv[j] = as[kk][tx * 4 + j];
            #pragma unroll
            for (int i = 0; i < 4; i++)
                #pragma unroll
                for (int j = 0; j < 4; j++) acc[i][j] += a[i] * bv[j];
        }
        __syncthreads();
    }
    #pragma unroll
    for (int i = 0; i < 4; i++) {
        int co = co0 + ty * 4 + i;
        float bv = bias[co];
        #pragma unroll
        for (int j = 0; j < 4; j++)
            out[(b * CC + co) * NN + p0 + tx * 4 + j] = acc[i][j] + bv;
    }
}

extern "C" void kernel_launch(void* const* d_in, const int* in_sizes, int n_in,
                              void* d_out, int out_size) {
    const float* x      = (const float*)d_in[0];
    const float* qkv_w  = (const float*)d_in[1];
    const float* qkv_b  = (const float*)d_in[2];
    const float* pos_w  = (const float*)d_in[3];
    const float* pos_b  = (const float*)d_in[4];
    const float* proj_w = (const float*)d_in[5];
    const float* proj_b = (const float*)d_in[6];
    const float* g1w    = (const float*)d_in[7];
    const float* g1b    = (const float*)d_in[8];
    const float* g2w    = (const float*)d_in[9];
    const float* g2b    = (const float*)d_in[10];
    float* out = (float*)d_out;

    k_zero<<<(BH * NN + 255) / 256, 256>>>();
    k_qkv<<<dim3(13, 6, 2), 256>>>(x, qkv_w, qkv_b);
    k_dw<<<(BB * C3 * NN + 255) / 256, 256>>>(pos_w, pos_b);
    k_qk<<<dim3(13, 13, 16), 256>>>();
    k_gate<<<BH, 256>>>(g1w, g1b, g2w, g2b);
    k_select<<<BH * NN / 4, 128>>>();
    k_pv<<<dim3(25, 16), 128>>>();
    k_proj<<<dim3(25, 4, 2), 256>>>(proj_w, proj_b, out);
}

// round 4
// speedup vs baseline: 1.5063x; 1.0790x over previous
#include <cuda_runtime.h>
#include <math.h>

#define BB 2
#define CC 256
#define NHEADS 8
#define HD 32
#define NN 1600
#define C3 768
#define BH 16
#define SCALE 0.17677669529663687f  // 1/sqrt(32)

// ---------------- scratch (static device memory; no allocations) ----------------
__device__ float g_qkv0[BB * C3 * NN];
__device__ float g_qkv1[BB * C3 * NN];
__device__ float g_attn[(size_t)BH * NN * NN];     // stores e = exp(logit)  (all > 0)
__device__ float g_S[BH * NN];
__device__ float g_T[BH * NN];
__device__ int   g_keep[BH];
__device__ float g_attout[BB * NN * CC];

// ---------------- helpers ----------------
__device__ __forceinline__ unsigned int f2key(float f) {
    // for positive floats: order-preserving key = bits | msb
    return __float_as_uint(f) | 0x80000000u;
}
__device__ __forceinline__ float key2f(unsigned int k) {
    return __uint_as_float(k ^ 0x80000000u);
}

__device__ __forceinline__ float bsum(float v, volatile float* sh) {
    #pragma unroll
    for (int o = 16; o; o >>= 1) v += __shfl_xor_sync(0xffffffffu, v, o);
    if ((threadIdx.x & 31) == 0) sh[threadIdx.x >> 5] = v;
    __syncthreads();
    if (threadIdx.x == 0) {
        float r = 0.f;
        #pragma unroll
        for (int i = 0; i < 8; i++) r += sh[i];
        sh[0] = r;
    }
    __syncthreads();
    float r = sh[0];
    __syncthreads();
    return r;
}

// ---------------- K0: zero stat accumulators ----------------
__global__ void k_zero() {
    int i = blockIdx.x * 256 + threadIdx.x;
    if (i < BH * NN) { g_S[i] = 0.f; g_T[i] = 0.f; }
}

// ---------------- K1: QKV 1x1 conv, 128x128 tile, 8x8/thread ----------------
__global__ __launch_bounds__(256, 2) void k_qkv(const float* __restrict__ x,
                                                const float* __restrict__ w,
                                                const float* __restrict__ bias) {
    __shared__ float ws[128][33];
    __shared__ float xs[32][128];
    int b = blockIdx.z;
    int oc0 = blockIdx.y * 128, p0 = blockIdx.x * 128;
    int tid = threadIdx.x, tx = tid & 15, ty = tid >> 4;
    float acc[8][8] = {};
    for (int k0 = 0; k0 < 256; k0 += 32) {
        #pragma unroll
        for (int l = 0; l < 4; l++) {
            int f = tid + 256 * l;
            int oc = f >> 3, k4 = f & 7;
            float4 v = *(const float4*)&w[(oc0 + oc) * 256 + k0 + k4 * 4];
            ws[oc][k4 * 4 + 0] = v.x; ws[oc][k4 * 4 + 1] = v.y;
            ws[oc][k4 * 4 + 2] = v.z; ws[oc][k4 * 4 + 3] = v.w;
        }
        #pragma unroll
        for (int l = 0; l < 4; l++) {
            int f = tid + 256 * l;
            int d = f >> 5, c4 = f & 31;
            int col = p0 + c4 * 4;
            float4 v = make_float4(0.f, 0.f, 0.f, 0.f);
            if (col < NN) v = *(const float4*)&x[(b * 256 + k0 + d) * NN + col];
            *(float4*)&xs[d][c4 * 4] = v;
        }
        __syncthreads();
        #pragma unroll
        for (int d = 0; d < 32; d++) {
            float a[8], bv[8];
            #pragma unroll
            for (int i = 0; i < 8; i++) a[i] = ws[ty * 8 + i][d];
            *(float4*)&bv[0] = *(float4*)&xs[d][tx * 8];
            *(float4*)&bv[4] = *(float4*)&xs[d][tx * 8 + 4];
            #pragma unroll
            for (int i = 0; i < 8; i++)
                #pragma unroll
                for (int j = 0; j < 8; j++) acc[i][j] += a[i] * bv[j];
        }
        __syncthreads();
    }
    int col0 = p0 + tx * 8;
    if (col0 < NN) {
        #pragma unroll
        for (int i = 0; i < 8; i++) {
            int oc = oc0 + ty * 8 + i;
            float bv = bias[oc];
            float o[8];
            #pragma unroll
            for (int j = 0; j < 8; j++) o[j] = acc[i][j] + bv;
            *(float4*)&g_qkv0[(b * C3 + oc) * NN + col0]     = *(float4*)&o[0];
            *(float4*)&g_qkv0[(b * C3 + oc) * NN + col0 + 4] = *(float4*)&o[4];
        }
    }
}

// ---------------- K2: depthwise 3x3, pad=1 ----------------
__global__ void k_dw(const float* __restrict__ pw, const float* __restrict__ pb) {
    int gid = blockIdx.x * 256 + threadIdx.x;
    if (gid >= BB * C3 * NN) return;
    int pix = gid % NN;
    int ch = (gid / NN) % C3;
    int b = gid / (NN * C3);
    int y = pix / 40, x = pix % 40;
    const float* src = g_qkv0 + (b * C3 + ch) * NN;
    const float* wp = pw + ch * 9;
    float s = pb[ch];
    #pragma unroll
    for (int ky = 0; ky < 3; ky++) {
        int yy = y + ky - 1;
        if (yy < 0 || yy >= 40) continue;
        #pragma unroll
        for (int kx = 0; kx < 3; kx++) {
            int xx = x + kx - 1;
            if (xx < 0 || xx >= 40) continue;
            s += wp[ky * 3 + kx] * src[yy * 40 + xx];
        }
    }
    g_qkv1[gid] = s;
}

// ---------------- K3: e = exp(scale*QK^T) stored; fused entropy stats ----------------
__global__ __launch_bounds__(256, 2) void k_qk() {
    __shared__ float qs[32][128];
    __shared__ float ks[32][128];
    int bh = blockIdx.z;
    int b = bh >> 3, h = bh & 7;
    int i0 = blockIdx.y * 128, j0 = blockIdx.x * 128;
    int tid = threadIdx.x, tx = tid & 15, ty = tid >> 4;
    const float* qp = g_qkv1 + (b * C3 + h * HD) * NN;
    const float* kp = g_qkv1 + (b * C3 + 256 + h * HD) * NN;
    #pragma unroll
    for (int l = 0; l < 4; l++) {
        int f = tid + 256 * l;
        int d = f >> 5, c4 = f & 31;
        int ci = i0 + c4 * 4, cj = j0 + c4 * 4;
        float4 vq = make_float4(0.f, 0.f, 0.f, 0.f);
        float4 vk = make_float4(0.f, 0.f, 0.f, 0.f);
        if (ci < NN) vq = *(const float4*)&qp[d * NN + ci];
        if (cj < NN) vk = *(const float4*)&kp[d * NN + cj];
        *(float4*)&qs[d][c4 * 4] = vq;
        *(float4*)&ks[d][c4 * 4] = vk;
    }
    __syncthreads();
    float acc[8][8] = {};
    #pragma unroll
    for (int d = 0; d < 32; d++) {
        float a[8], bv[8];
        *(float4*)&a[0]  = *(float4*)&qs[d][ty * 8];
        *(float4*)&a[4]  = *(float4*)&qs[d][ty * 8 + 4];
        *(float4*)&bv[0] = *(float4*)&ks[d][tx * 8];
        *(float4*)&bv[4] = *(float4*)&ks[d][tx * 8 + 4];
        #pragma unroll
        for (int i = 0; i < 8; i++)
            #pragma unroll
            for (int j = 0; j < 8; j++) acc[i][j] += a[i] * bv[j];
    }
    float* outp = g_attn + (size_t)bh * NN * NN;
    int col0 = j0 + tx * 8;
    bool colok = (col0 < NN);
    #pragma unroll
    for (int i = 0; i < 8; i++) {
        int rowi = i0 + ty * 8 + i;
        if (rowi >= NN) continue;
        float se = 0.f, te = 0.f;
        float ev[8];
        #pragma unroll
        for (int j = 0; j < 8; j++) {
            float a = acc[i][j] * SCALE;
            float e = expf(a);
            ev[j] = e;
            se += e;
            te += a * e;
        }
        if (colok) {
            *(float4*)&outp[(size_t)rowi * NN + col0]     = *(float4*)&ev[0];
            *(float4*)&outp[(size_t)rowi * NN + col0 + 4] = *(float4*)&ev[4];
        } else { se = 0.f; te = 0.f; }
        #pragma unroll
        for (int o = 8; o; o >>= 1) {
            se += __shfl_xor_sync(0xffffffffu, se, o);
            te += __shfl_xor_sync(0xffffffffu, te, o);
        }
        if (tx == 0) {
            atomicAdd(&g_S[bh * NN + rowi], se);
            atomicAdd(&g_T[bh * NN + rowi], te);
        }
    }
}

// ---------------- K4: entropy gate MLP -> keep per (b,h) ----------------
__global__ void k_gate(const float* __restrict__ g1w, const float* __restrict__ g1b,
                       const float* __restrict__ g2w, const float* __restrict__ g2b) {
    int bh = blockIdx.x;
    __shared__ float sh[8];
    float s = 0.f;
    for (int i = threadIdx.x; i < NN; i += 256) {
        float S = g_S[bh * NN + i];
        float T = g_T[bh * NN + i];
        s += logf(S) - T / S;
    }
    s = bsum(s, sh);
    if (threadIdx.x == 0) {
        float e = s / (float)NN;
        float z = g2b[0];
        #pragma unroll
        for (int i = 0; i < 16; i++) {
            float hid = fmaxf(e * g1w[i] + g1b[i], 0.f);
            z += hid * g2w[i];
        }
        float ratio = 1.f / (1.f + expf(-z)) * 0.9f + 0.1f;
        int keep = (int)ceilf(ratio * (float)NN);
        keep = min(max(keep, 1), NN);
        g_keep[bh] = keep;
    }
}

// ---------------- K5: fused select + PV. grid (25,16), 256 threads ----------------
// dyn smem: phase1 keys[8][1600] (51200B) + hist[8][256] (8192B)  => 59392B
//           phase2 ps[64][68] (17408B) + vs[64][36] (9216B) overlap same pool
#define SPV_SMEM 59392
__global__ __launch_bounds__(256) void k_spv() {
    extern __shared__ float pool[];
    unsigned int* keybuf = (unsigned int*)pool;                 // [8][1600]
    unsigned int* hist   = (unsigned int*)(pool + 8 * 1600);    // [8][256]
    float* ps = pool;                // [64][68]  (phase 2)
    float* vs = pool + 64 * 68;      // [64][36]  (phase 2)
    __shared__ float thf[64];
    __shared__ float ivs[64];

    int bh = blockIdx.y;
    int b = bh >> 3, h = bh & 7;
    int row0 = blockIdx.x * 64;
    int tid = threadIdx.x, w = tid >> 5, lane = tid & 31;
    const float* A = g_attn + (size_t)bh * NN * NN;
    int keep = g_keep[bh];

    // ---- phase 1: warp-per-row radix select, 8 rows per warp ----
    unsigned int* kv = keybuf + w * 1600;
    unsigned int* hh = hist + w * 256;
    for (int i = 0; i < 8; i++) {
        int r = w * 8 + i;
        const float4* src = (const float4*)(A + (size_t)(row0 + r) * NN);
        for (int t = lane; t < 400; t += 32) {
            float4 v = src[t];
            ((uint4*)kv)[t] = make_uint4(f2key(v.x), f2key(v.y), f2key(v.z), f2key(v.w));
        }
        __syncwarp();
        int rem = keep;
        unsigned int pref = 0;
        #pragma unroll
        for (int rd = 3; rd >= 0; rd--) {
            ((uint4*)hh)[lane]      = make_uint4(0u, 0u, 0u, 0u);
            ((uint4*)hh)[lane + 32] = make_uint4(0u, 0u, 0u, 0u);
            __syncwarp();
            for (int t = 0; t < 50; t++) {
                unsigned int key = kv[t * 32 + lane];
                bool part = (rd == 3) || ((key >> ((rd + 1) * 8)) == pref);
                if (part) atomicAdd(&hh[(key >> (rd * 8)) & 0xFFu], 1u);
            }
            __syncwarp();
            unsigned int bins[8], loc[8];
            #pragma unroll
            for (int k = 0; k < 8; k++) bins[k] = hh[lane * 8 + k];
            loc[7] = bins[7];
            #pragma unroll
            for (int k = 6; k >= 0; k--) loc[k] = loc[k + 1] + bins[k];
            unsigned int lsum = loc[0];
            unsigned int v = lsum;
            #pragma unroll
            for (int off = 1; off < 32; off <<= 1) {
                unsigned int o = __shfl_down_sync(0xffffffffu, v, off);
                if (lane + off < 32) v += o;
            }
            unsigned int above = v - lsum;
            int foundk = -1;
            int newrem = 0;
            #pragma unroll
            for (int k = 0; k < 8; k++) {
                unsigned int cum = loc[k] + above;
                unsigned int cumn = ((k < 7) ? loc[k + 1] : 0u) + above;
                if (cum >= (unsigned int)rem && cumn < (unsigned int)rem) {
                    foundk = k;
                    newrem = rem - (int)cumn;
                }
            }
            unsigned int ball = __ballot_sync(0xffffffffu, foundk >= 0);
            int src_l = __ffs(ball) - 1;
            int bb = __shfl_sync(0xffffffffu, lane * 8 + foundk, src_l);
            rem = __shfl_sync(0xffffffffu, newrem, src_l);
            pref = (pref << 8) | (unsigned int)bb;
            __syncwarp();
        }
        float S = 0.f;
        for (int t = 0; t < 50; t++) {
            unsigned int key = kv[t * 32 + lane];
            if (key >= pref) S += key2f(key);
        }
        #pragma unroll
        for (int o = 16; o; o >>= 1) S += __shfl_xor_sync(0xffffffffu, S, o);
        if (lane == 0) {
            thf[r] = key2f(pref);
            ivs[r] = 1.f / S;
        }
    }
    __syncthreads();

    // ---- phase 2: out = P @ V^T, p on the fly (L2-hot re-read) ----
    const float* V = g_qkv1 + (b * C3 + 512 + h * HD) * NN;
    int tx = tid & 7, ty = tid >> 3;     // tx: 4-col group (32 cols), ty: 2-row group (64 rows)
    float acc[2][4] = {};
    for (int j0 = 0; j0 < NN; j0 += 64) {
        __syncthreads();
        #pragma unroll
        for (int l = 0; l < 4; l++) {
            int f = tid + 256 * l;
            int rr = f >> 4, c4 = f & 15;
            float4 e4 = *(const float4*)&A[(size_t)(row0 + rr) * NN + j0 + c4 * 4];
            float th = thf[rr], ivv = ivs[rr];
            float4 pp;
            pp.x = (e4.x >= th) ? e4.x * ivv : 0.f;
            pp.y = (e4.y >= th) ? e4.y * ivv : 0.f;
            pp.z = (e4.z >= th) ? e4.z * ivv : 0.f;
            pp.w = (e4.w >= th) ? e4.w * ivv : 0.f;
            *(float4*)&ps[rr * 68 + c4 * 4] = pp;
        }
        #pragma unroll
        for (int l = 0; l < 2; l++) {
            int f = tid + 256 * l;
            int d = f >> 4, j4 = f & 15;
            float4 vv = *(const float4*)&V[d * NN + j0 + j4 * 4];
            vs[(j4 * 4 + 0) * 36 + d] = vv.x;
            vs[(j4 * 4 + 1) * 36 + d] = vv.y;
            vs[(j4 * 4 + 2) * 36 + d] = vv.z;
            vs[(j4 * 4 + 3) * 36 + d] = vv.w;
        }
        __syncthreads();
        #pragma unroll
        for (int jj = 0; jj < 64; jj += 4) {
            float pr[2][4], vr[4][4];
            #pragma unroll
            for (int r = 0; r < 2; r++)
                *(float4*)pr[r] = *(float4*)&ps[(ty * 2 + r) * 68 + jj];
            #pragma unroll
            for (int k = 0; k < 4; k++)
                *(float4*)vr[k] = *(float4*)&vs[(jj + k) * 36 + tx * 4];
            #pragma unroll
            for (int r = 0; r < 2; r++)
                #pragma unroll
                for (int k = 0; k < 4; k++)
                    #pragma unroll
                    for (int c = 0; c < 4; c++) acc[r][c] += pr[r][k] * vr[k][c];
        }
    }
    #pragma unroll
    for (int r = 0; r < 2; r++)
        *(float4*)&g_attout[(size_t)(b * NN + row0 + ty * 2 + r) * CC + h * HD + tx * 4]
            = *(float4*)acc[r];
}

// ---------------- K7: output projection + final transpose ----------------
__global__ void k_proj(const float* __restrict__ w, const float* __restrict__ bias,
                       float* __restrict__ out) {
    __shared__ float ws[32][65];
    __shared__ float as[32][65];
    int b = blockIdx.z;
    int co0 = blockIdx.y * 64, p0 = blockIdx.x * 64;
    int tid = threadIdx.x, tx = tid & 15, ty = tid >> 4;
    float acc[4][4] = {};
    for (int k0 = 0; k0 < 256; k0 += 32) {
        #pragma unroll
        for (int l = 0; l < 8; l++) {
            int idx = tid + 256 * l;
            int r = idx >> 5, c = idx & 31;
            ws[c][r] = w[(co0 + r) * 256 + k0 + c];
        }
        #pragma unroll
        for (int l = 0; l < 8; l++) {
            int idx = tid + 256 * l;
            int p = idx >> 5, c = idx & 31;
            as[c][p] = g_attout[(size_t)(b * NN + p0 + p) * CC + k0 + c];
        }
        __syncthreads();
        #pragma unroll
        for (int kk = 0; kk < 32; kk++) {
            float a[4], bv[4];
            #pragma unroll
            for (int i = 0; i < 4; i++) a[i] = ws[kk][ty * 4 + i];
            #pragma unroll
            for (int j = 0; j < 4; j++) bv[j] = as[kk][tx * 4 + j];
            #pragma unroll
            for (int i = 0; i < 4; i++)
                #pragma unroll
                for (int j = 0; j < 4; j++) acc[i][j] += a[i] * bv[j];
        }
        __syncthreads();
    }
    #pragma unroll
    for (int i = 0; i < 4; i++) {
        int co = co0 + ty * 4 + i;
        float bv = bias[co];
        #pragma unroll
        for (int j = 0; j < 4; j++)
            out[(b * CC + co) * NN + p0 + tx * 4 + j] = acc[i][j] + bv;
    }
}

extern "C" void kernel_launch(void* const* d_in, const int* in_sizes, int n_in,
                              void* d_out, int out_size) {
    const float* x      = (const float*)d_in[0];
    const float* qkv_w  = (const float*)d_in[1];
    const float* qkv_b  = (const float*)d_in[2];
    const float* pos_w  = (const float*)d_in[3];
    const float* pos_b  = (const float*)d_in[4];
    const float* proj_w = (const float*)d_in[5];
    const float* proj_b = (const float*)d_in[6];
    const float* g1w    = (const float*)d_in[7];
    const float* g1b    = (const float*)d_in[8];
    const float* g2w    = (const float*)d_in[9];
    const float* g2b    = (const float*)d_in[10];
    float* out = (float*)d_out;

    static int configured = 0;
    if (!configured) {
        cudaFuncSetAttribute(k_spv, cudaFuncAttributeMaxDynamicSharedMemorySize, SPV_SMEM);
        configured = 1;
    }

    k_zero<<<(BH * NN + 255) / 256, 256>>>();
    k_qkv<<<dim3(13, 6, 2), 256>>>(x, qkv_w, qkv_b);
    k_dw<<<(BB * C3 * NN + 255) / 256, 256>>>(pos_w, pos_b);
    k_qk<<<dim3(13, 13, 16), 256>>>();
    k_gate<<<BH, 256>>>(g1w, g1b, g2w, g2b);
    k_spv<<<dim3(25, 16), 256, SPV_SMEM>>>();
    k_proj<<<dim3(25, 4, 2), 256>>>(proj_w, proj_b, out);
}

// round 5
// speedup vs baseline: 1.7460x; 1.1591x over previous
#include <cuda_runtime.h>
#include <math.h>

#define BB 2
#define CC 256
#define NHEADS 8
#define HD 32
#define NN 1600
#define C3 768
#define BH 16
#define SCALE 0.17677669529663687f  // 1/sqrt(32)

// ---------------- scratch (static device memory; no allocations) ----------------
__device__ float g_qkv0[BB * C3 * NN];
__device__ float g_qkv1[BB * C3 * NN];
__device__ float g_attn[(size_t)BH * NN * NN];     // stores e = exp(logit)  (all > 0)
__device__ float g_S[BH * NN];
__device__ float g_T[BH * NN];
__device__ int   g_keep[BH];
__device__ float g_attout[BB * NN * CC];

// ---------------- helpers ----------------
__device__ __forceinline__ float key2f(unsigned int k) {
    return __uint_as_float(k ^ 0x80000000u);
}

__device__ __forceinline__ float bsum(float v, volatile float* sh) {
    #pragma unroll
    for (int o = 16; o; o >>= 1) v += __shfl_xor_sync(0xffffffffu, v, o);
    if ((threadIdx.x & 31) == 0) sh[threadIdx.x >> 5] = v;
    __syncthreads();
    if (threadIdx.x == 0) {
        float r = 0.f;
        #pragma unroll
        for (int i = 0; i < 8; i++) r += sh[i];
        sh[0] = r;
    }
    __syncthreads();
    float r = sh[0];
    __syncthreads();
    return r;
}

// match-aggregated histogram add; byte==0xFFFFFFFF is a no-op lane
__device__ __forceinline__ void hadd(unsigned int* hh, unsigned int byte_or_dummy) {
    unsigned int peers = __match_any_sync(0xffffffffu, byte_or_dummy);
    int lane = threadIdx.x & 31;
    if (byte_or_dummy <= 255u && lane == (__ffs(peers) - 1))
        atomicAdd(&hh[byte_or_dummy], (unsigned int)__popc(peers));
}

// warp radix-round selection: given 256-bin hist, descending rank rem,
// returns the chosen byte and updates rem to rank within that bin.
__device__ __forceinline__ unsigned int warp_sel(const unsigned int* hh, int& rem) {
    int lane = threadIdx.x & 31;
    unsigned int bins[8], loc[8];
    #pragma unroll
    for (int k = 0; k < 8; k++) bins[k] = hh[lane * 8 + k];
    loc[7] = bins[7];
    #pragma unroll
    for (int k = 6; k >= 0; k--) loc[k] = loc[k + 1] + bins[k];
    unsigned int lsum = loc[0];
    unsigned int v = lsum;
    #pragma unroll
    for (int off = 1; off < 32; off <<= 1) {
        unsigned int o = __shfl_down_sync(0xffffffffu, v, off);
        if (lane + off < 32) v += o;
    }
    unsigned int above = v - lsum;
    int foundk = -1;
    int newrem = 0;
    #pragma unroll
    for (int k = 0; k < 8; k++) {
        unsigned int cum = loc[k] + above;
        unsigned int cumn = ((k < 7) ? loc[k + 1] : 0u) + above;
        if (cum >= (unsigned int)rem && cumn < (unsigned int)rem) {
            foundk = k;
            newrem = rem - (int)cumn;
        }
    }
    unsigned int ball = __ballot_sync(0xffffffffu, foundk >= 0);
    int src = __ffs(ball) - 1;
    unsigned int b = (unsigned int)__shfl_sync(0xffffffffu, lane * 8 + foundk, src);
    rem = __shfl_sync(0xffffffffu, newrem, src);
    return b;
}

// ---------------- K0: zero stat accumulators ----------------
__global__ void k_zero() {
    int i = blockIdx.x * 256 + threadIdx.x;
    if (i < BH * NN) { g_S[i] = 0.f; g_T[i] = 0.f; }
}

// ---------------- K1: QKV 1x1 conv, 128x128 tile, 8x8/thread ----------------
__global__ __launch_bounds__(256, 2) void k_qkv(const float* __restrict__ x,
                                                const float* __restrict__ w,
                                                const float* __restrict__ bias) {
    __shared__ float ws[128][33];
    __shared__ float xs[32][128];
    int b = blockIdx.z;
    int oc0 = blockIdx.y * 128, p0 = blockIdx.x * 128;
    int tid = threadIdx.x, tx = tid & 15, ty = tid >> 4;
    float acc[8][8] = {};
    for (int k0 = 0; k0 < 256; k0 += 32) {
        #pragma unroll
        for (int l = 0; l < 4; l++) {
            int f = tid + 256 * l;
            int oc = f >> 3, k4 = f & 7;
            float4 v = *(const float4*)&w[(oc0 + oc) * 256 + k0 + k4 * 4];
            ws[oc][k4 * 4 + 0] = v.x; ws[oc][k4 * 4 + 1] = v.y;
            ws[oc][k4 * 4 + 2] = v.z; ws[oc][k4 * 4 + 3] = v.w;
        }
        #pragma unroll
        for (int l = 0; l < 4; l++) {
            int f = tid + 256 * l;
            int d = f >> 5, c4 = f & 31;
            int col = p0 + c4 * 4;
            float4 v = make_float4(0.f, 0.f, 0.f, 0.f);
            if (col < NN) v = *(const float4*)&x[(b * 256 + k0 + d) * NN + col];
            *(float4*)&xs[d][c4 * 4] = v;
        }
        __syncthreads();
        #pragma unroll
        for (int d = 0; d < 32; d++) {
            float a[8], bv[8];
            #pragma unroll
            for (int i = 0; i < 8; i++) a[i] = ws[ty * 8 + i][d];
            *(float4*)&bv[0] = *(float4*)&xs[d][tx * 8];
            *(float4*)&bv[4] = *(float4*)&xs[d][tx * 8 + 4];
            #pragma unroll
            for (int i = 0; i < 8; i++)
                #pragma unroll
                for (int j = 0; j < 8; j++) acc[i][j] += a[i] * bv[j];
        }
        __syncthreads();
    }
    int col0 = p0 + tx * 8;
    if (col0 < NN) {
        #pragma unroll
        for (int i = 0; i < 8; i++) {
            int oc = oc0 + ty * 8 + i;
            float bv = bias[oc];
            float o[8];
            #pragma unroll
            for (int j = 0; j < 8; j++) o[j] = acc[i][j] + bv;
            *(float4*)&g_qkv0[(b * C3 + oc) * NN + col0]     = *(float4*)&o[0];
            *(float4*)&g_qkv0[(b * C3 + oc) * NN + col0 + 4] = *(float4*)&o[4];
        }
    }
}

// ---------------- K2: depthwise 3x3, pad=1 ----------------
__global__ void k_dw(const float* __restrict__ pw, const float* __restrict__ pb) {
    int gid = blockIdx.x * 256 + threadIdx.x;
    if (gid >= BB * C3 * NN) return;
    int pix = gid % NN;
    int ch = (gid / NN) % C3;
    int b = gid / (NN * C3);
    int y = pix / 40, x = pix % 40;
    const float* src = g_qkv0 + (b * C3 + ch) * NN;
    const float* wp = pw + ch * 9;
    float s = pb[ch];
    #pragma unroll
    for (int ky = 0; ky < 3; ky++) {
        int yy = y + ky - 1;
        if (yy < 0 || yy >= 40) continue;
        #pragma unroll
        for (int kx = 0; kx < 3; kx++) {
            int xx = x + kx - 1;
            if (xx < 0 || xx >= 40) continue;
            s += wp[ky * 3 + kx] * src[yy * 40 + xx];
        }
    }
    g_qkv1[gid] = s;
}

// ---------------- K3: e = exp(scale*QK^T) stored; fused entropy stats ----------------
__global__ __launch_bounds__(256, 2) void k_qk() {
    __shared__ float qs[32][128];
    __shared__ float ks[32][128];
    int bh = blockIdx.z;
    int b = bh >> 3, h = bh & 7;
    int i0 = blockIdx.y * 128, j0 = blockIdx.x * 128;
    int tid = threadIdx.x, tx = tid & 15, ty = tid >> 4;
    const float* qp = g_qkv1 + (b * C3 + h * HD) * NN;
    const float* kp = g_qkv1 + (b * C3 + 256 + h * HD) * NN;
    #pragma unroll
    for (int l = 0; l < 4; l++) {
        int f = tid + 256 * l;
        int d = f >> 5, c4 = f & 31;
        int ci = i0 + c4 * 4, cj = j0 + c4 * 4;
        float4 vq = make_float4(0.f, 0.f, 0.f, 0.f);
        float4 vk = make_float4(0.f, 0.f, 0.f, 0.f);
        if (ci < NN) vq = *(const float4*)&qp[d * NN + ci];
        if (cj < NN) vk = *(const float4*)&kp[d * NN + cj];
        *(float4*)&qs[d][c4 * 4] = vq;
        *(float4*)&ks[d][c4 * 4] = vk;
    }
    __syncthreads();
    float acc[8][8] = {};
    #pragma unroll
    for (int d = 0; d < 32; d++) {
        float a[8], bv[8];
        *(float4*)&a[0]  = *(float4*)&qs[d][ty * 8];
        *(float4*)&a[4]  = *(float4*)&qs[d][ty * 8 + 4];
        *(float4*)&bv[0] = *(float4*)&ks[d][tx * 8];
        *(float4*)&bv[4] = *(float4*)&ks[d][tx * 8 + 4];
        #pragma unroll
        for (int i = 0; i < 8; i++)
            #pragma unroll
            for (int j = 0; j < 8; j++) acc[i][j] += a[i] * bv[j];
    }
    float* outp = g_attn + (size_t)bh * NN * NN;
    int col0 = j0 + tx * 8;
    bool colok = (col0 < NN);
    #pragma unroll
    for (int i = 0; i < 8; i++) {
        int rowi = i0 + ty * 8 + i;
        if (rowi >= NN) continue;
        float se = 0.f, te = 0.f;
        float ev[8];
        #pragma unroll
        for (int j = 0; j < 8; j++) {
            float a = acc[i][j] * SCALE;
            float e = expf(a);
            ev[j] = e;
            se += e;
            te += a * e;
        }
        if (colok) {
            *(float4*)&outp[(size_t)rowi * NN + col0]     = *(float4*)&ev[0];
            *(float4*)&outp[(size_t)rowi * NN + col0 + 4] = *(float4*)&ev[4];
        } else { se = 0.f; te = 0.f; }
        #pragma unroll
        for (int o = 8; o; o >>= 1) {
            se += __shfl_xor_sync(0xffffffffu, se, o);
            te += __shfl_xor_sync(0xffffffffu, te, o);
        }
        if (tx == 0) {
            atomicAdd(&g_S[bh * NN + rowi], se);
            atomicAdd(&g_T[bh * NN + rowi], te);
        }
    }
}

// ---------------- K4: entropy gate MLP -> keep per (b,h) ----------------
__global__ void k_gate(const float* __restrict__ g1w, const float* __restrict__ g1b,
                       const float* __restrict__ g2w, const float* __restrict__ g2b) {
    int bh = blockIdx.x;
    __shared__ float sh[8];
    float s = 0.f;
    for (int i = threadIdx.x; i < NN; i += 256) {
        float S = g_S[bh * NN + i];
        float T = g_T[bh * NN + i];
        s += logf(S) - T / S;
    }
    s = bsum(s, sh);
    if (threadIdx.x == 0) {
        float e = s / (float)NN;
        float z = g2b[0];
        #pragma unroll
        for (int i = 0; i < 16; i++) {
            float hid = fmaxf(e * g1w[i] + g1b[i], 0.f);
            z += hid * g2w[i];
        }
        float ratio = 1.f / (1.f + expf(-z)) * 0.9f + 0.1f;
        int keep = (int)ceilf(ratio * (float)NN);
        keep = min(max(keep, 1), NN);
        g_keep[bh] = keep;
    }
}

// ---------------- K5: fused select + PV ----------------
// dyn smem layout:
//   phase1: keybuf[8][1600] + hist[8][256] + cand[8][256] = 67584 B
//   phase2: ps[64][68] + vs[64][36] + red[64][32]         = 34816 B (overlaps)
#define SPV_SMEM 67584
__global__ __launch_bounds__(256) void k_spv() {
    extern __shared__ float pool[];
    unsigned int* keybuf = (unsigned int*)pool;                      // 8*1600
    unsigned int* histb  = (unsigned int*)pool + 8 * 1600;           // 8*256
    unsigned int* candb  = (unsigned int*)pool + 8 * 1600 + 8 * 256; // 8*256
    float* ps  = pool;                       // [64][68]
    float* vs  = pool + 64 * 68;             // [64][36]
    float* red = pool + 64 * 68 + 64 * 36;   // [64][32]
    __shared__ float thf[64];
    __shared__ float ivs[64];

    int bh = blockIdx.y;
    int b = bh >> 3, h = bh & 7;
    int row0 = blockIdx.x * 64;
    int tid = threadIdx.x, w = tid >> 5, lane = tid & 31;
    unsigned int lmask = (1u << lane) - 1u;
    const float* A = g_attn + (size_t)bh * NN * NN;
    int keep = g_keep[bh];

    unsigned int* kv = keybuf + w * 1600;
    unsigned int* hh = histb + w * 256;
    unsigned int* cd = candb + w * 256;

    // ---- phase 1: warp-per-row select, 8 rows per warp ----
    for (int i = 0; i < 8; i++) {
        int r = w * 8 + i;
        const uint4* src = (const uint4*)(A + (size_t)(row0 + r) * NN);
        ((uint4*)hh)[lane]      = make_uint4(0u, 0u, 0u, 0u);
        ((uint4*)hh)[lane + 32] = make_uint4(0u, 0u, 0u, 0u);
        __syncwarp();
        // pass A: load + keyify + round-1 hist + total sum
        float Sall = 0.f;
        for (int t = 0; t < 13; t++) {
            int idx = t * 32 + lane;
            bool ok = idx < 400;
            uint4 kk = make_uint4(0u, 0u, 0u, 0u);
            if (ok) {
                kk = src[idx];
                kk.x |= 0x80000000u; kk.y |= 0x80000000u;
                kk.z |= 0x80000000u; kk.w |= 0x80000000u;
                ((uint4*)kv)[idx] = kk;
                Sall += key2f(kk.x) + key2f(kk.y) + key2f(kk.z) + key2f(kk.w);
            }
            hadd(hh, ok ? (kk.x >> 24) : 0xFFFFFFFFu);
            hadd(hh, ok ? (kk.y >> 24) : 0xFFFFFFFFu);
            hadd(hh, ok ? (kk.z >> 24) : 0xFFFFFFFFu);
            hadd(hh, ok ? (kk.w >> 24) : 0xFFFFFFFFu);
        }
        #pragma unroll
        for (int o = 16; o; o >>= 1) Sall += __shfl_xor_sync(0xffffffffu, Sall, o);
        if (keep == NN) {       // everything kept: threshold 0 (all e > 0)
            if (lane == 0) { thf[r] = 0.f; ivs[r] = 1.f / Sall; }
            continue;
        }
        __syncwarp();
        int rem = keep;
        unsigned int b3 = warp_sel(hh, rem);
        // pass B: round-2 hist within top-byte bin
        ((uint4*)hh)[lane]      = make_uint4(0u, 0u, 0u, 0u);
        ((uint4*)hh)[lane + 32] = make_uint4(0u, 0u, 0u, 0u);
        __syncwarp();
        for (int t = 0; t < 13; t++) {
            int idx = t * 32 + lane;
            bool ok = idx < 400;
            uint4 kk = ok ? ((const uint4*)kv)[idx] : make_uint4(0u, 0u, 0u, 0u);
            hadd(hh, (ok && (kk.x >> 24) == b3) ? ((kk.x >> 16) & 0xFFu) : 0xFFFFFFFFu);
            hadd(hh, (ok && (kk.y >> 24) == b3) ? ((kk.y >> 16) & 0xFFu) : 0xFFFFFFFFu);
            hadd(hh, (ok && (kk.z >> 24) == b3) ? ((kk.z >> 16) & 0xFFu) : 0xFFFFFFFFu);
            hadd(hh, (ok && (kk.w >> 24) == b3) ? ((kk.w >> 16) & 0xFFu) : 0xFFFFFFFFu);
        }
        __syncwarp();
        unsigned int b2 = warp_sel(hh, rem);
        unsigned int pref16 = (b3 << 8) | b2;
        // pass C: compact candidates (top16 == pref16) + sum of strictly-higher bins
        int cnt = 0;
        float sum_hi = 0.f;
        for (int t = 0; t < 13; t++) {
            int idx = t * 32 + lane;
            bool ok = idx < 400;
            uint4 kk = ok ? ((const uint4*)kv)[idx] : make_uint4(0u, 0u, 0u, 0u);
            #define CPROC(KEY)                                                      \
            {                                                                       \
                unsigned int hi = (KEY) >> 16;                                      \
                bool isc = ok && (hi == pref16);                                    \
                if (ok && hi > pref16) sum_hi += key2f(KEY);                        \
                unsigned int bal = __ballot_sync(0xffffffffu, isc);                 \
                if (isc) {                                                          \
                    int pos = cnt + __popc(bal & lmask);                            \
                    if (pos < 256) cd[pos] = (KEY);                                 \
                }                                                                   \
                cnt += __popc(bal);                                                 \
            }
            CPROC(kk.x) CPROC(kk.y) CPROC(kk.z) CPROC(kk.w)
            #undef CPROC
        }
        __syncwarp();
        unsigned int pref;
        float Spart;
        if (cnt <= 256) {
            int iters = (cnt + 31) >> 5;
            // round 3 on candidates
            ((uint4*)hh)[lane]      = make_uint4(0u, 0u, 0u, 0u);
            ((uint4*)hh)[lane + 32] = make_uint4(0u, 0u, 0u, 0u);
            __syncwarp();
            for (int t = 0; t < iters; t++) {
                int idx = t * 32 + lane;
                bool ok = idx < cnt;
                unsigned int key = ok ? cd[idx] : 0u;
                hadd(hh, ok ? ((key >> 8) & 0xFFu) : 0xFFFFFFFFu);
            }
            __syncwarp();
            unsigned int b1 = warp_sel(hh, rem);
            // round 4 on candidates
            ((uint4*)hh)[lane]      = make_uint4(0u, 0u, 0u, 0u);
            ((uint4*)hh)[lane + 32] = make_uint4(0u, 0u, 0u, 0u);
            __syncwarp();
            for (int t = 0; t < iters; t++) {
                int idx = t * 32 + lane;
                bool ok = idx < cnt;
                unsigned int key = ok ? cd[idx] : 0u;
                hadd(hh, (ok && ((key >> 8) & 0xFFu) == b1) ? (key & 0xFFu) : 0xFFFFFFFFu);
            }
            __syncwarp();
            unsigned int b0 = warp_sel(hh, rem);
            pref = (pref16 << 16) | (b1 << 8) | b0;
            float Sc = 0.f;
            for (int t = 0; t < iters; t++) {
                int idx = t * 32 + lane;
                if (idx < cnt) {
                    unsigned int key = cd[idx];
                    if (key >= pref) Sc += key2f(key);
                }
            }
            Spart = sum_hi + Sc;
        } else {
            // fallback: full-scan rounds 3-4 (rare: >256 keys share 16-bit prefix)
            ((uint4*)hh)[lane]      = make_uint4(0u, 0u, 0u, 0u);
            ((uint4*)hh)[lane + 32] = make_uint4(0u, 0u, 0u, 0u);
            __syncwarp();
            for (int t = 0; t < 50; t++) {
                int idx = t * 32 + lane;
                unsigned int key = kv[idx];
                hadd(hh, ((key >> 16) == pref16) ? ((key >> 8) & 0xFFu) : 0xFFFFFFFFu);
            }
            __syncwarp();
            unsigned int b1 = warp_sel(hh, rem);
            unsigned int pref24 = (pref16 << 8) | b1;
            ((uint4*)hh)[lane]      = make_uint4(0u, 0u, 0u, 0u);
            ((uint4*)hh)[lane + 32] = make_uint4(0u, 0u, 0u, 0u);
            __syncwarp();
            for (int t = 0; t < 50; t++) {
                int idx = t * 32 + lane;
                unsigned int key = kv[idx];
                hadd(hh, ((key >> 8) == pref24) ? (key & 0xFFu) : 0xFFFFFFFFu);
            }
            __syncwarp();
            unsigned int b0 = warp_sel(hh, rem);
            pref = (pref24 << 8) | b0;
            float Sf = 0.f;
            for (int t = 0; t < 50; t++) {
                unsigned int key = kv[t * 32 + lane];
                if (key >= pref) Sf += key2f(key);
            }
            Spart = Sf;
        }
        #pragma unroll
        for (int o = 16; o; o >>= 1) Spart += __shfl_xor_sync(0xffffffffu, Spart, o);
        if (lane == 0) {
            thf[r] = key2f(pref);
            ivs[r] = 1.f / Spart;
        }
    }
    __syncthreads();

    // ---- phase 2: out = P @ V^T, p on the fly, K split across 2 thread-groups ----
    const float* V = g_qkv1 + (b * C3 + 512 + h * HD) * NN;
    int g = tid >> 7;                // K-group 0/1
    int t1 = tid & 127;
    int tx = t1 & 7, ty = t1 >> 3;   // tx: 4-col group (32 cols), ty: 4-row group (64 rows)
    float acc[4][4] = {};
    for (int j0 = 0; j0 < NN; j0 += 64) {
        __syncthreads();
        #pragma unroll
        for (int l = 0; l < 4; l++) {
            int f = tid + 256 * l;
            int rr = f >> 4, c4 = f & 15;
            float4 e4 = *(const float4*)&A[(size_t)(row0 + rr) * NN + j0 + c4 * 4];
            float th = thf[rr], ivv = ivs[rr];
            float4 pp;
            pp.x = (e4.x >= th) ? e4.x * ivv : 0.f;
            pp.y = (e4.y >= th) ? e4.y * ivv : 0.f;
            pp.z = (e4.z >= th) ? e4.z * ivv : 0.f;
            pp.w = (e4.w >= th) ? e4.w * ivv : 0.f;
            *(float4*)&ps[rr * 68 + c4 * 4] = pp;
        }
        #pragma unroll
        for (int l = 0; l < 2; l++) {
            int f = tid + 256 * l;
            int d = f >> 4, j4 = f & 15;
            float4 vv = *(const float4*)&V[d * NN + j0 + j4 * 4];
            vs[(j4 * 4 + 0) * 36 + d] = vv.x;
            vs[(j4 * 4 + 1) * 36 + d] = vv.y;
            vs[(j4 * 4 + 2) * 36 + d] = vv.z;
            vs[(j4 * 4 + 3) * 36 + d] = vv.w;
        }
        __syncthreads();
        int jbase = g * 32;
        #pragma unroll
        for (int jj = 0; jj < 32; jj += 4) {
            float pr[4][4], vr[4][4];
            #pragma unroll
            for (int r = 0; r < 4; r++)
                *(float4*)pr[r] = *(float4*)&ps[(ty * 4 + r) * 68 + jbase + jj];
            #pragma unroll
            for (int k = 0; k < 4; k++)
                *(float4*)vr[k] = *(float4*)&vs[(jbase + jj + k) * 36 + tx * 4];
            #pragma unroll
            for (int r = 0; r < 4; r++)
                #pragma unroll
                for (int k = 0; k < 4; k++)
                    #pragma unroll
                    for (int c = 0; c < 4; c++) acc[r][c] += pr[r][k] * vr[k][c];
        }
    }
    __syncthreads();
    if (g == 1) {
        #pragma unroll
        for (int r = 0; r < 4; r++)
            *(float4*)&red[(ty * 4 + r) * 32 + tx * 4] = *(float4*)acc[r];
    }
    __syncthreads();
    if (g == 0) {
        #pragma unroll
        for (int r = 0; r < 4; r++) {
            #pragma unroll
            for (int c = 0; c < 4; c++) acc[r][c] += red[(ty * 4 + r) * 32 + tx * 4 + c];
            *(float4*)&g_attout[(size_t)(b * NN + row0 + ty * 4 + r) * CC + h * HD + tx * 4]
                = *(float4*)acc[r];
        }
    }
}

// ---------------- K7: output projection + final transpose ----------------
__global__ void k_proj(const float* __restrict__ w, const float* __restrict__ bias,
                       float* __restrict__ out) {
    __shared__ float ws[32][65];
    __shared__ float as[32][65];
    int b = blockIdx.z;
    int co0 = blockIdx.y * 64, p0 = blockIdx.x * 64;
    int tid = threadIdx.x, tx = tid & 15, ty = tid >> 4;
    float acc[4][4] = {};
    for (int k0 = 0; k0 < 256; k0 += 32) {
        #pragma unroll
        for (int l = 0; l < 8; l++) {
            int idx = tid + 256 * l;
            int r = idx >> 5, c = idx & 31;
            ws[c][r] = w[(co0 + r) * 256 + k0 + c];
        }
        #pragma unroll
        for (int l = 0; l < 8; l++) {
            int idx = tid + 256 * l;
            int p = idx >> 5, c = idx & 31;
            as[c][p] = g_attout[(size_t)(b * NN + p0 + p) * CC + k0 + c];
        }
        __syncthreads();
        #pragma unroll
        for (int kk = 0; kk < 32; kk++) {
            float a[4], bv[4];
            #pragma unroll
            for (int i = 0; i < 4; i++) a[i] = ws[kk][ty * 4 + i];
            #pragma unroll
            for (int j = 0; j < 4; j++) bv[j] = as[kk][tx * 4 + j];
            #pragma unroll
            for (int i = 0; i < 4; i++)
                #pragma unroll
                for (int j = 0; j < 4; j++) acc[i][j] += a[i] * bv[j];
        }
        __syncthreads();
    }
    #pragma unroll
    for (int i = 0; i < 4; i++) {
        int co = co0 + ty * 4 + i;
        float bv = bias[co];
        #pragma unroll
        for (int j = 0; j < 4; j++)
            out[(b * CC + co) * NN + p0 + tx * 4 + j] = acc[i][j] + bv;
    }
}

extern "C" void kernel_launch(void* const* d_in, const int* in_sizes, int n_in,
                              void* d_out, int out_size) {
    const float* x      = (const float*)d_in[0];
    const float* qkv_w  = (const float*)d_in[1];
    const float* qkv_b  = (const float*)d_in[2];
    const float* pos_w  = (const float*)d_in[3];
    const float* pos_b  = (const float*)d_in[4];
    const float* proj_w = (const float*)d_in[5];
    const float* proj_b = (const float*)d_in[6];
    const float* g1w    = (const float*)d_in[7];
    const float* g1b    = (const float*)d_in[8];
    const float* g2w    = (const float*)d_in[9];
    const float* g2b    = (const float*)d_in[10];
    float* out = (float*)d_out;

    static int configured = 0;
    if (!configured) {
        cudaFuncSetAttribute(k_spv, cudaFuncAttributeMaxDynamicSharedMemorySize, SPV_SMEM);
        configured = 1;
    }

    k_zero<<<(BH * NN + 255) / 256, 256>>>();
    k_qkv<<<dim3(13, 6, 2), 256>>>(x, qkv_w, qkv_b);
    k_dw<<<(BB * C3 * NN + 255) / 256, 256>>>(pos_w, pos_b);
    k_qk<<<dim3(13, 13, 16), 256>>>();
    k_gate<<<BH, 256>>>(g1w, g1b, g2w, g2b);
    k_spv<<<dim3(25, 16), 256, SPV_SMEM>>>();
    k_proj<<<dim3(25, 4, 2), 256>>>(proj_w, proj_b, out);
}